// round 17
// baseline (speedup 1.0000x reference)
#include <cuda_runtime.h>
#include <cuda_bf16.h>
#include <math_constants.h>

#define N_NODES  2000000
#define DEPTH    128
#define N_GRAPHS 4096
#define ROWS_PER_BLOCK 512
#define THREADS_R 256
#define ROWS_PER_WARP 64      // 512 rows / 8 warps
#define GT 16                 // graphs per block in MLP kernel

// Scratch accumulators (allocation-free: __device__ globals)
__device__ float g_sum[N_GRAPHS * DEPTH];
__device__ float g_max[N_GRAPHS * DEPTH];
__device__ int   g_cnt[N_GRAPHS];

__device__ __forceinline__ void atomicMaxF(float* addr, float v) {
    // monotonic-bits trick (inputs are finite, no NaNs)
    if (v >= 0.0f) atomicMax((int*)addr, __float_as_int(v));
    else           atomicMin((unsigned int*)addr, __float_as_uint(v));
}

// Vectorized init
__global__ __launch_bounds__(256) void init_kernel() {
    int i = blockIdx.x * 256 + threadIdx.x;           // grid = 512 blocks
    float4 z = make_float4(0.f, 0.f, 0.f, 0.f);
    float4 m = make_float4(-CUDART_INF_F, -CUDART_INF_F, -CUDART_INF_F, -CUDART_INF_F);
    ((float4*)g_sum)[i] = z;
    ((float4*)g_max)[i] = m;
    if (i < N_GRAPHS) g_cnt[i] = 0;
}

// One block = 512 consecutive rows; warp w owns 64 contiguous rows.
// Lane c owns float4 column c. batch is sorted -> contiguous segments;
// accumulate in registers, flush atomics at boundaries.
// Inner batch of 8 LDG.128 per warp (4KB in flight) to hide DRAM latency.
__global__ __launch_bounds__(THREADS_R) void reduce_kernel(
    const float4* __restrict__ x4, const int* __restrict__ batch)
{
    __shared__ int s_batch[ROWS_PER_BLOCK];
    const int tid  = threadIdx.x;
    const int w    = tid >> 5;
    const int c    = tid & 31;
    const int base = blockIdx.x * ROWS_PER_BLOCK;
    const int nrow = min(ROWS_PER_BLOCK, N_NODES - base);   // 512 or 128

    for (int i = tid; i < nrow; i += THREADS_R)
        s_batch[i] = batch[base + i];
    __syncthreads();

    const int rstart = w * ROWS_PER_WARP;
    if (rstart >= nrow) return;          // last block: warps 2..7 idle
    // nrow is a multiple of 64 -> each active warp has exactly 64 rows

    int    cur  = s_batch[rstart];
    float4 ls   = make_float4(0.f, 0.f, 0.f, 0.f);
    float4 lm   = make_float4(-CUDART_INF_F, -CUDART_INF_F, -CUDART_INF_F, -CUDART_INF_F);
    int    lcnt = 0;

    const float4* p = x4 + (size_t)(base + rstart) * 32 + c;

    for (int r = rstart; r < rstart + ROWS_PER_WARP; r += 8) {
        float4 v[8];
        #pragma unroll
        for (int i = 0; i < 8; i++)
            v[i] = __ldcs(p + (size_t)i * 32);
        p += 8 * 32;

        #pragma unroll
        for (int i = 0; i < 8; i++) {
            int g = s_batch[r + i];
            if (g != cur) {
                float* ps = &g_sum[cur * DEPTH + 4 * c];
                atomicAdd(ps + 0, ls.x); atomicAdd(ps + 1, ls.y);
                atomicAdd(ps + 2, ls.z); atomicAdd(ps + 3, ls.w);
                float* pm = &g_max[cur * DEPTH + 4 * c];
                atomicMaxF(pm + 0, lm.x); atomicMaxF(pm + 1, lm.y);
                atomicMaxF(pm + 2, lm.z); atomicMaxF(pm + 3, lm.w);
                if (c == 0) atomicAdd(&g_cnt[cur], lcnt);
                cur = g; lcnt = 0;
                ls = make_float4(0.f, 0.f, 0.f, 0.f);
                lm = make_float4(-CUDART_INF_F, -CUDART_INF_F, -CUDART_INF_F, -CUDART_INF_F);
            }
            ls.x += v[i].x; ls.y += v[i].y; ls.z += v[i].z; ls.w += v[i].w;
            lm.x = fmaxf(lm.x, v[i].x); lm.y = fmaxf(lm.y, v[i].y);
            lm.z = fmaxf(lm.z, v[i].z); lm.w = fmaxf(lm.w, v[i].w);
            lcnt++;
        }
    }
    // tail flush
    {
        float* ps = &g_sum[cur * DEPTH + 4 * c];
        atomicAdd(ps + 0, ls.x); atomicAdd(ps + 1, ls.y);
        atomicAdd(ps + 2, ls.z); atomicAdd(ps + 3, ls.w);
        float* pm = &g_max[cur * DEPTH + 4 * c];
        atomicMaxF(pm + 0, lm.x); atomicMaxF(pm + 1, lm.y);
        atomicMaxF(pm + 2, lm.z); atomicMaxF(pm + 3, lm.w);
        if (c == 0) atomicAdd(&g_cnt[cur], lcnt);
    }
}

// MLP over 4096 graphs. 64 threads/block; thread j owns output dims j and
// j+64, so each sc/sh LDS.128 feeds 8 FFMAs (halves LDS traffic vs 1 dim).
__global__ __launch_bounds__(64) void mlp_kernel(
    const float* __restrict__ W1, const float* __restrict__ b1,
    const float* __restrict__ W2, const float* __restrict__ b2,
    float* __restrict__ out)
{
    __shared__ float sc[GT][3 * DEPTH]; // concat vectors  (24 KB)
    __shared__ float sh[GT][DEPTH];     // hidden vectors  ( 8 KB)
    const int j  = threadIdx.x;         // 0..63
    const int g0 = blockIdx.x * GT;

    // fill concat: each thread handles feature dims j and j+64
    #pragma unroll
    for (int g = 0; g < GT; g++) {
        int gg = g0 + g;
        int cnt = g_cnt[gg];
        float inv = 1.0f / fmaxf((float)cnt, 1.0f);
        #pragma unroll
        for (int h = 0; h < 2; h++) {
            int d = j + h * 64;
            float s = g_sum[gg * DEPTH + d];
            float m = g_max[gg * DEPTH + d];
            sc[g][d]             = (cnt > 0) ? m : 0.0f;
            sc[g][DEPTH + d]     = s * inv;
            sc[g][2 * DEPTH + d] = s;
        }
    }
    __syncthreads();

    float accA[GT], accB[GT];
    {
        float bA = b1[j], bB = b1[j + 64];
        #pragma unroll
        for (int g = 0; g < GT; g++) { accA[g] = bA; accB[g] = bB; }
        const float4* w1a = (const float4*)(W1 + (size_t)j        * (3 * DEPTH));
        const float4* w1b = (const float4*)(W1 + (size_t)(j + 64) * (3 * DEPTH));
        #pragma unroll 4
        for (int k4 = 0; k4 < (3 * DEPTH) / 4; k4++) {
            float4 wa = w1a[k4];
            float4 wb = w1b[k4];
            #pragma unroll
            for (int g = 0; g < GT; g++) {
                float4 cc = *(const float4*)&sc[g][k4 * 4];
                accA[g] += wa.x * cc.x + wa.y * cc.y + wa.z * cc.z + wa.w * cc.w;
                accB[g] += wb.x * cc.x + wb.y * cc.y + wb.z * cc.z + wb.w * cc.w;
            }
        }
        #pragma unroll
        for (int g = 0; g < GT; g++) {
            float hA = accA[g], hB = accB[g];
            sh[g][j]      = (hA > 0.0f) ? hA : 0.01f * hA;   // leaky_relu 0.01
            sh[g][j + 64] = (hB > 0.0f) ? hB : 0.01f * hB;
        }
    }
    __syncthreads();
    {
        float bA = b2[j], bB = b2[j + 64];
        #pragma unroll
        for (int g = 0; g < GT; g++) { accA[g] = bA; accB[g] = bB; }
        const float4* w2a = (const float4*)(W2 + (size_t)j        * DEPTH);
        const float4* w2b = (const float4*)(W2 + (size_t)(j + 64) * DEPTH);
        #pragma unroll 4
        for (int k4 = 0; k4 < DEPTH / 4; k4++) {
            float4 wa = w2a[k4];
            float4 wb = w2b[k4];
            #pragma unroll
            for (int g = 0; g < GT; g++) {
                float4 h = *(const float4*)&sh[g][k4 * 4];
                accA[g] += wa.x * h.x + wa.y * h.y + wa.z * h.z + wa.w * h.w;
                accB[g] += wb.x * h.x + wb.y * h.y + wb.z * h.z + wb.w * h.w;
            }
        }
        #pragma unroll
        for (int g = 0; g < GT; g++) {
            out[(size_t)(g0 + g) * DEPTH + j]      = accA[g];
            out[(size_t)(g0 + g) * DEPTH + j + 64] = accB[g];
        }
    }
}

extern "C" void kernel_launch(void* const* d_in, const int* in_sizes, int n_in,
                              void* d_out, int out_size)
{
    const float* x  = nullptr; const int* batch = nullptr;
    const float* W1 = nullptr; const float* b1 = nullptr;
    const float* W2 = nullptr; const float* b2 = nullptr;
    for (int i = 0; i < n_in; i++) {
        long s = in_sizes[i];
        if      (s == (long)N_NODES * DEPTH)   x     = (const float*)d_in[i];
        else if (s == (long)N_NODES)           batch = (const int*)  d_in[i];
        else if (s == (long)DEPTH * 3 * DEPTH) W1    = (const float*)d_in[i];
        else if (s == (long)DEPTH * DEPTH)     W2    = (const float*)d_in[i];
        else if (s == (long)DEPTH) { if (!b1) b1 = (const float*)d_in[i];
                                     else     b2 = (const float*)d_in[i]; }
    }

    init_kernel<<<(N_GRAPHS * DEPTH / 4) / 256, 256>>>();

    int nblocks = (N_NODES + ROWS_PER_BLOCK - 1) / ROWS_PER_BLOCK;
    reduce_kernel<<<nblocks, THREADS_R>>>((const float4*)x, batch);

    mlp_kernel<<<N_GRAPHS / GT, 64>>>(W1, b1, W2, b2, (float*)d_out);
}